// round 1
// baseline (speedup 1.0000x reference)
#include <cuda_runtime.h>
#include <cuda_bf16.h>
#include <math.h>

// Problem constants
#define BB 1
#define HH 64
#define WW 64
#define CC 256
#define HEADS 8
#define HD 32
#define KK 7
#define DIL 2
#define FF 1024
#define NTOK (HH*WW)            // 4096
#define SCALE 0.17677669529663687f  // 1/sqrt(32)

// ---------------- scratch (device globals; no runtime alloc) ----------------
__device__ float g_hs  [NTOK*CC];      // LN1(x)
__device__ float g_qkv [NTOK*3*CC];    // [tok][q|k|v] concatenated
__device__ float g_ctx [NTOK*CC];      // attention context
__device__ float g_hs2 [NTOK*CC];      // x + attn_out
__device__ float g_y   [NTOK*CC];      // LN2(hs2)
__device__ float g_t   [NTOK*FF];      // gelu(y@w1+b1)
__device__ float g_wqkv[CC*3*CC];      // packed [256][768]
__device__ float g_bqkv[3*CC];

// ---------------- weight pack: wq|wk|wv -> [256][768] ----------------
__global__ void pack_kernel(const float* __restrict__ wq, const float* __restrict__ wk,
                            const float* __restrict__ wv, const float* __restrict__ bq,
                            const float* __restrict__ bk, const float* __restrict__ bv)
{
    int idx = blockIdx.x * 256 + threadIdx.x;
    if (idx < CC*3*CC) {
        int r = idx / (3*CC), c = idx % (3*CC);
        float v;
        if      (c < CC)   v = wq[r*CC + c];
        else if (c < 2*CC) v = wk[r*CC + (c - CC)];
        else               v = wv[r*CC + (c - 2*CC)];
        g_wqkv[idx] = v;
    }
    if (idx < 3*CC) {
        float v;
        if      (idx < CC)   v = bq[idx];
        else if (idx < 2*CC) v = bk[idx - CC];
        else                 v = bv[idx - 2*CC];
        g_bqkv[idx] = v;
    }
}

// ---------------- LayerNorm: one block per row, 256 threads ----------------
__global__ void ln_kernel(const float* __restrict__ x, const float* __restrict__ g,
                          const float* __restrict__ b, float* __restrict__ out)
{
    int row = blockIdx.x;
    int c   = threadIdx.x;       // 0..255
    float v = x[row*CC + c];
    float s = v, sq = v*v;
    #pragma unroll
    for (int o = 16; o; o >>= 1) {
        s  += __shfl_xor_sync(0xffffffffu, s,  o);
        sq += __shfl_xor_sync(0xffffffffu, sq, o);
    }
    __shared__ float rs[8], rq[8];
    int w = c >> 5, l = c & 31;
    if (l == 0) { rs[w] = s; rq[w] = sq; }
    __syncthreads();
    // first warp reduces the 8 partials; broadcast via shared
    if (w == 0) {
        float ss = (l < 8) ? rs[l] : 0.f;
        float qq = (l < 8) ? rq[l] : 0.f;
        #pragma unroll
        for (int o = 16; o; o >>= 1) {
            ss += __shfl_xor_sync(0xffffffffu, ss, o);
            qq += __shfl_xor_sync(0xffffffffu, qq, o);
        }
        if (l == 0) { rs[0] = ss; rq[0] = qq; }
    }
    __syncthreads();
    float mean = rs[0] * (1.0f/CC);
    float var  = rq[0] * (1.0f/CC) - mean*mean;
    float inv  = rsqrtf(var + 1e-5f);
    out[row*CC + c] = (v - mean) * inv * g[c] + b[c];
}

// ---------------- tiled fp32 GEMM: C[M,N] = A[M,K] @ W[K,N] (+ epilogue) ----
// EPI 0: +bias ; EPI 1: gelu(+bias) exact ; EPI 2: +bias + res
#define BM 64
#define BN 64
#define BKT 16

template<int EPI>
__global__ void gemm_kernel(const float* __restrict__ A, const float* __restrict__ W,
                            const float* __restrict__ bias, const float* __restrict__ res,
                            float* __restrict__ C, int M, int N, int K)
{
    __shared__ float As[BM][BKT];
    __shared__ float Ws[BKT][BN];
    const int tx = threadIdx.x, ty = threadIdx.y;       // 16 x 16
    const int tid = ty*16 + tx;
    const int bm = blockIdx.y * BM, bn = blockIdx.x * BN;

    float acc[4][4] = {};
    for (int k0 = 0; k0 < K; k0 += BKT) {
        #pragma unroll
        for (int l = 0; l < 4; l++) {
            int idx = tid + l*256;
            int r = idx >> 4, c = idx & 15;
            As[r][c] = A[(size_t)(bm + r)*K + k0 + c];
        }
        #pragma unroll
        for (int l = 0; l < 4; l++) {
            int idx = tid + l*256;
            int r = idx >> 6, c = idx & 63;
            Ws[r][c] = W[(size_t)(k0 + r)*N + bn + c];
        }
        __syncthreads();
        #pragma unroll
        for (int kk = 0; kk < BKT; kk++) {
            float a[4], bfr[4];
            #pragma unroll
            for (int i = 0; i < 4; i++) a[i] = As[ty*4 + i][kk];
            #pragma unroll
            for (int j = 0; j < 4; j++) bfr[j] = Ws[kk][tx*4 + j];
            #pragma unroll
            for (int i = 0; i < 4; i++)
                #pragma unroll
                for (int j = 0; j < 4; j++)
                    acc[i][j] = fmaf(a[i], bfr[j], acc[i][j]);
        }
        __syncthreads();
    }

    #pragma unroll
    for (int i = 0; i < 4; i++) {
        int row = bm + ty*4 + i;
        #pragma unroll
        for (int j = 0; j < 4; j++) {
            int col = bn + tx*4 + j;
            float v = acc[i][j] + bias[col];
            if (EPI == 1) {
                v = v * normcdff(v);              // exact GELU: x * Phi(x)
            } else if (EPI == 2) {
                v += res[(size_t)row*N + col];
            }
            C[(size_t)row*N + col] = v;
        }
    }
}

// ---------------- dilated neighborhood attention ----------------
// one warp per (token, head); block = (32, 8) -> 8 heads, grid = NTOK
__global__ void attn_kernel(const float* __restrict__ qkv, const float* __restrict__ rpb,
                            float* __restrict__ ctx)
{
    __shared__ float sc[HEADS][52];
    const int tok  = blockIdx.x;
    const int head = threadIdx.y;
    const int lane = threadIdx.x;
    const int i = tok >> 6, j = tok & 63;

    // clamped dilated-window starts (L=64, k=7, d=2 -> lg=32, max start=25)
    int gi = i >> 1, ri = i & 1;
    int si = gi - 3; si = si < 0 ? 0 : (si > 25 ? 25 : si);
    int gj = j >> 1, rj = j & 1;
    int sj = gj - 3; sj = sj < 0 ? 0 : (sj > 25 ? 25 : sj);

    const int qoff = head*HD + lane;
    const float q = qkv[(size_t)tok*(3*CC) + qoff] * SCALE;
    const float* biasrow = rpb + head*169;   // 13*13
    const int bhi = si - gi + 6;             // bias row base
    const int bwj = sj - gj + 6;             // bias col base

    // pass 1: scores
    #pragma unroll
    for (int kh = 0; kh < KK; kh++) {
        int ki = (si + kh)*2 + ri;
        #pragma unroll
        for (int kw = 0; kw < KK; kw++) {
            int kj = (sj + kw)*2 + rj;
            int nt = ki*WW + kj;
            float kv = qkv[(size_t)nt*(3*CC) + CC + qoff];
            float s = q * kv;
            #pragma unroll
            for (int o = 16; o; o >>= 1) s += __shfl_xor_sync(0xffffffffu, s, o);
            if (lane == 0)
                sc[head][kh*KK + kw] = s + biasrow[(bhi + kh)*13 + (bwj + kw)];
        }
    }
    __syncwarp();

    // softmax over 49
    float m = -1e30f;
    for (int n = lane; n < 49; n += 32) m = fmaxf(m, sc[head][n]);
    #pragma unroll
    for (int o = 16; o; o >>= 1) m = fmaxf(m, __shfl_xor_sync(0xffffffffu, m, o));
    float ssum = 0.f;
    for (int n = lane; n < 49; n += 32) {
        float e = expf(sc[head][n] - m);
        sc[head][n] = e;
        ssum += e;
    }
    #pragma unroll
    for (int o = 16; o; o >>= 1) ssum += __shfl_xor_sync(0xffffffffu, ssum, o);
    __syncwarp();
    const float inv = 1.0f / ssum;

    // pass 2: weighted V
    float cacc = 0.f;
    #pragma unroll
    for (int kh = 0; kh < KK; kh++) {
        int ki = (si + kh)*2 + ri;
        #pragma unroll
        for (int kw = 0; kw < KK; kw++) {
            int kj = (sj + kw)*2 + rj;
            int nt = ki*WW + kj;
            float vv = qkv[(size_t)nt*(3*CC) + 2*CC + qoff];
            cacc = fmaf(sc[head][kh*KK + kw], vv, cacc);
        }
    }
    ctx[(size_t)tok*CC + qoff] = cacc * inv;
}

// ---------------- launch ----------------
extern "C" void kernel_launch(void* const* d_in, const int* in_sizes, int n_in,
                              void* d_out, int out_size)
{
    const float* x     = (const float*)d_in[0];
    const float* ln1_g = (const float*)d_in[1];
    const float* ln1_b = (const float*)d_in[2];
    const float* wq    = (const float*)d_in[3];
    const float* bq    = (const float*)d_in[4];
    const float* wk    = (const float*)d_in[5];
    const float* bk    = (const float*)d_in[6];
    const float* wv    = (const float*)d_in[7];
    const float* bv    = (const float*)d_in[8];
    const float* rpb   = (const float*)d_in[9];
    const float* wo    = (const float*)d_in[10];
    const float* bo    = (const float*)d_in[11];
    const float* ln2_g = (const float*)d_in[12];
    const float* ln2_b = (const float*)d_in[13];
    const float* w1    = (const float*)d_in[14];
    const float* b1    = (const float*)d_in[15];
    const float* w2    = (const float*)d_in[16];
    const float* b2    = (const float*)d_in[17];
    float* out = (float*)d_out;

    float *hs, *qkv, *ctx, *hs2, *y, *t, *wqkv, *bqkv;
    cudaGetSymbolAddress((void**)&hs,   g_hs);
    cudaGetSymbolAddress((void**)&qkv,  g_qkv);
    cudaGetSymbolAddress((void**)&ctx,  g_ctx);
    cudaGetSymbolAddress((void**)&hs2,  g_hs2);
    cudaGetSymbolAddress((void**)&y,    g_y);
    cudaGetSymbolAddress((void**)&t,    g_t);
    cudaGetSymbolAddress((void**)&wqkv, g_wqkv);
    cudaGetSymbolAddress((void**)&bqkv, g_bqkv);

    // 1) pack qkv weights
    pack_kernel<<<(CC*3*CC + 255)/256, 256>>>(wq, wk, wv, bq, bk, bv);

    // 2) LN1
    ln_kernel<<<NTOK, CC>>>(x, ln1_g, ln1_b, hs);

    // 3) QKV GEMM: [4096,256] @ [256,768]
    {
        dim3 grid((3*CC)/BN, NTOK/BM), blk(16, 16);
        gemm_kernel<0><<<grid, blk>>>(hs, wqkv, bqkv, nullptr, qkv, NTOK, 3*CC, CC);
    }

    // 4) attention
    {
        dim3 blk(32, HEADS);
        attn_kernel<<<NTOK, blk>>>(qkv, rpb, ctx);
    }

    // 5) wo GEMM + residual(x): hs2 = ctx@wo + bo + x
    {
        dim3 grid(CC/BN, NTOK/BM), blk(16, 16);
        gemm_kernel<2><<<grid, blk>>>(ctx, wo, bo, x, hs2, NTOK, CC, CC);
    }

    // 6) LN2
    ln_kernel<<<NTOK, CC>>>(hs2, ln2_g, ln2_b, y);

    // 7) w1 GEMM + exact GELU: t = gelu(y@w1 + b1)
    {
        dim3 grid(FF/BN, NTOK/BM), blk(16, 16);
        gemm_kernel<1><<<grid, blk>>>(y, w1, b1, nullptr, t, NTOK, FF, CC);
    }

    // 8) w2 GEMM + residual(hs2): out = t@w2 + b2 + hs2
    {
        dim3 grid(CC/BN, NTOK/BM), blk(16, 16);
        gemm_kernel<2><<<grid, blk>>>(t, w2, b2, hs2, out, NTOK, CC, FF);
    }
}